// round 2
// baseline (speedup 1.0000x reference)
#include <cuda_runtime.h>

#define NTOK 49
#define CDIM 128
#define HEADS 4
#define HD 32
#define THREADS 384

static constexpr float SCALE = 0.17677669529663687f; // 32^-0.5

// smem layout (floats):
//   s_x   : [128][52]  transposed x (phase 1/2); overlaid by o_nc [49][132] in phase 3/4
//   s_qkv : [49][388]  qkv activations (q:0..127, k:128..255, v:256..383)
//   s_msk : [49*49]    shift mask for this window
#define SX_STRIDE   52
#define QKV_STRIDE  388
#define ONC_STRIDE  132
#define SX_FLOATS   (128 * SX_STRIDE)            // 6656
#define QKV_FLOATS  (NTOK * QKV_STRIDE)          // 19012
#define MSK_FLOATS  (NTOK * NTOK)                // 2401
#define SMEM_FLOATS (SX_FLOATS + QKV_FLOATS + MSK_FLOATS)
#define SMEM_BYTES  (SMEM_FLOATS * 4)            // 112276 B

typedef unsigned long long ull;

__device__ __forceinline__ ull pk2(float lo, float hi) {
    ull r; asm("mov.b64 %0, {%1, %2};" : "=l"(r) : "f"(lo), "f"(hi)); return r;
}
__device__ __forceinline__ void upk2(ull v, float& lo, float& hi) {
    asm("mov.b64 {%0, %1}, %2;" : "=f"(lo), "=f"(hi) : "l"(v));
}
__device__ __forceinline__ ull fma2(ull a, ull b, ull c) {
    ull d; asm("fma.rn.f32x2 %0, %1, %2, %3;" : "=l"(d) : "l"(a), "l"(b), "l"(c)); return d;
}

__global__ void __launch_bounds__(THREADS)
win_attn_kernel(const float* __restrict__ x,
                const float* __restrict__ qkv_w,
                const float* __restrict__ proj_w,
                const float* __restrict__ proj_b,
                const float* __restrict__ table,
                const float* __restrict__ mask,
                const int*   __restrict__ pidx,
                float* __restrict__ out,
                int nW)
{
    extern __shared__ float smem[];
    float* s_x   = smem;                  // [128][52], later o_nc [49][132]
    float* s_qkv = smem + SX_FLOATS;      // [49][388]
    float* s_msk = s_qkv + QKV_FLOATS;    // [49*49]

    const int b = blockIdx.x;
    const int t = threadIdx.x;

    // ---------------- Phase 1: load x (transposed) + mask ----------------
    {
        const float4* x4 = (const float4*)(x + (size_t)b * NTOK * CDIM);
        #pragma unroll 1
        for (int i = t; i < NTOK * CDIM / 4; i += THREADS) {
            float4 v = __ldg(x4 + i);
            int n  = i >> 5;            // 32 float4 per token row
            int c4 = (i & 31) << 2;
            s_x[(c4 + 0) * SX_STRIDE + n] = v.x;
            s_x[(c4 + 1) * SX_STRIDE + n] = v.y;
            s_x[(c4 + 2) * SX_STRIDE + n] = v.z;
            s_x[(c4 + 3) * SX_STRIDE + n] = v.w;
        }
        const float* mrow = mask + (size_t)(b % nW) * NTOK * NTOK;
        #pragma unroll 1
        for (int i = t; i < NTOK * NTOK; i += THREADS)
            s_msk[i] = __ldg(mrow + i);
    }
    __syncthreads();

    // ---------------- Phase 2: qkv = x @ qkv_w^T, thread t = column o=t ----
    {
        ull a2[24];
        float a48 = 0.f;
        #pragma unroll
        for (int i = 0; i < 24; i++) a2[i] = 0ull;

        const float4* w4p = (const float4*)(qkv_w + t * CDIM);
        #pragma unroll 2
        for (int cc = 0; cc < 32; cc++) {
            float4 w4 = __ldg(w4p + cc);
            #pragma unroll
            for (int j = 0; j < 4; j++) {
                float wv = (&w4.x)[j];
                ull wv2 = pk2(wv, wv);
                const int c = cc * 4 + j;
                const ulonglong2* xr = (const ulonglong2*)(s_x + c * SX_STRIDE);
                #pragma unroll
                for (int q = 0; q < 12; q++) {
                    ulonglong2 xv = xr[q];
                    a2[2 * q]     = fma2(wv2, xv.x, a2[2 * q]);
                    a2[2 * q + 1] = fma2(wv2, xv.y, a2[2 * q + 1]);
                }
                a48 = fmaf(wv, s_x[c * SX_STRIDE + 48], a48);
            }
        }
        #pragma unroll
        for (int i = 0; i < 24; i++) {
            float lo, hi; upk2(a2[i], lo, hi);
            s_qkv[(2 * i) * QKV_STRIDE + t]     = lo;
            s_qkv[(2 * i + 1) * QKV_STRIDE + t] = hi;
        }
        s_qkv[48 * QKV_STRIDE + t] = a48;
    }
    __syncthreads();

    // ---------------- Phase 3: attention per (head, row) -------------------
    if (t < HEADS * NTOK) {
        const int h = t / NTOK;
        const int n = t % NTOK;

        // pack q row into registers
        ull q2[16];
        {
            const ulonglong2* qrow = (const ulonglong2*)(s_qkv + n * QKV_STRIDE + h * HD);
            #pragma unroll
            for (int i = 0; i < 8; i++) {
                ulonglong2 v = qrow[i];
                q2[2 * i] = v.x; q2[2 * i + 1] = v.y;
            }
        }

        float p[NTOK];
        float mx = -1e30f;
        const int*   prow  = pidx + n * NTOK;
        const float* mkrow = s_msk + n * NTOK;

        #pragma unroll
        for (int m = 0; m < NTOK; m++) {
            const ulonglong2* krow =
                (const ulonglong2*)(s_qkv + m * QKV_STRIDE + CDIM + h * HD);
            ull sa = 0ull, sb = 0ull;
            #pragma unroll
            for (int i = 0; i < 8; i++) {
                ulonglong2 kv = krow[i];
                sa = fma2(q2[2 * i],     kv.x, sa);
                sb = fma2(q2[2 * i + 1], kv.y, sb);
            }
            float a0, a1, b0, b1; upk2(sa, a0, a1); upk2(sb, b0, b1);
            float dot = (a0 + a1) + (b0 + b1);
            int id = __ldg(prow + m);
            float s = fmaf(dot, SCALE, __ldg(table + id * 4 + h) + mkrow[m]);
            p[m] = s;
            mx = fmaxf(mx, s);
        }

        float sum = 0.f;
        #pragma unroll
        for (int m = 0; m < NTOK; m++) { p[m] = __expf(p[m] - mx); sum += p[m]; }
        float inv = 1.0f / sum;

        ull acc[16];
        #pragma unroll
        for (int i = 0; i < 16; i++) acc[i] = 0ull;
        #pragma unroll
        for (int m = 0; m < NTOK; m++) {
            ull pm2 = pk2(p[m], p[m]);
            const ulonglong2* vrow =
                (const ulonglong2*)(s_qkv + m * QKV_STRIDE + 2 * CDIM + h * HD);
            #pragma unroll
            for (int i = 0; i < 8; i++) {
                ulonglong2 vv = vrow[i];
                acc[2 * i]     = fma2(pm2, vv.x, acc[2 * i]);
                acc[2 * i + 1] = fma2(pm2, vv.y, acc[2 * i + 1]);
            }
        }

        float* orow = s_x + n * ONC_STRIDE + h * HD;   // o_nc overlay (x tile is dead)
        #pragma unroll
        for (int i = 0; i < 16; i++) {
            float lo, hi; upk2(acc[i], lo, hi);
            orow[2 * i]     = lo * inv;
            orow[2 * i + 1] = hi * inv;
        }
    }
    __syncthreads();

    // ---------------- Phase 4: out = o @ proj_w^T + b ----------------------
    {
        const int o  = t & 127;
        const int g  = t >> 7;            // 0,1,2
        const int n0 = g * 17;            // rows n0..n0+16 (g=2: only 15 valid, reads safe)

        ull acc[17];
        #pragma unroll
        for (int i = 0; i < 17; i++) acc[i] = 0ull;

        const float4* w4p = (const float4*)(proj_w + o * CDIM);
        #pragma unroll 2
        for (int cc = 0; cc < 32; cc++) {
            float4 w4 = __ldg(w4p + cc);
            ull wp0 = pk2(w4.x, w4.y);
            ull wp1 = pk2(w4.z, w4.w);
            #pragma unroll
            for (int i = 0; i < 17; i++) {
                ulonglong2 xv = ((const ulonglong2*)(s_x + (n0 + i) * ONC_STRIDE))[cc];
                acc[i] = fma2(wp0, xv.x, acc[i]);
                acc[i] = fma2(wp1, xv.y, acc[i]);
            }
        }

        float bias = __ldg(proj_b + o);
        float* obase = out + (size_t)b * NTOK * CDIM;
        #pragma unroll
        for (int i = 0; i < 17; i++) {
            int n = n0 + i;
            if (n < NTOK) {
                float lo, hi; upk2(acc[i], lo, hi);
                obase[n * CDIM + o] = lo + hi + bias;
            }
        }
    }
}

extern "C" void kernel_launch(void* const* d_in, const int* in_sizes, int n_in,
                              void* d_out, int out_size)
{
    const float* x      = (const float*)d_in[0];
    const float* qkv_w  = (const float*)d_in[1];
    const float* proj_w = (const float*)d_in[2];
    const float* proj_b = (const float*)d_in[3];
    const float* table  = (const float*)d_in[4];
    const float* mask   = (const float*)d_in[5];
    const int*   pidx   = (const int*)d_in[6];
    float* out = (float*)d_out;

    int B  = in_sizes[0] / (NTOK * CDIM);      // 8192
    int nW = in_sizes[5] / (NTOK * NTOK);      // 1024

    cudaFuncSetAttribute(win_attn_kernel,
                         cudaFuncAttributeMaxDynamicSharedMemorySize, SMEM_BYTES);
    win_attn_kernel<<<B, THREADS, SMEM_BYTES>>>(x, qkv_w, proj_w, proj_b,
                                                table, mask, pidx, out, nW);
}

// round 3
// speedup vs baseline: 1.1567x; 1.1567x over previous
#include <cuda_runtime.h>

#define NTOK 49
#define CDIM 128
#define HEADS 4
#define HD 32
#define THREADS 384

static constexpr float SCALE = 0.17677669529663687f; // 32^-0.5

// smem (floats):
//   s_x2  : [50][268]  x duplicated pairs (x,x) per channel; overlaid by o2 (same fmt) in phase 3/4
//   s_qkv : [50][388]  qkv activations (q:0..127, k:128..255, v:256..383)
//   s_msk : [49*49]
#define X2_STRIDE  268
#define QKV_STRIDE 388
#define X2_FLOATS  (50 * X2_STRIDE)     // 13400
#define QKV_FLOATS (50 * QKV_STRIDE)    // 19400
#define MSK_FLOATS (NTOK * NTOK)        // 2401
#define SMEM_FLOATS (X2_FLOATS + QKV_FLOATS + MSK_FLOATS)
#define SMEM_BYTES  (SMEM_FLOATS * 4)   // 140804 B

typedef unsigned long long ull;

__device__ float g_qkv_wt[CDIM * 3 * CDIM];     // [c][384]
__device__ float g_proj_wt[CDIM * CDIM];        // [c][128]
__device__ float g_pbias[HEADS * NTOK * NTOK];  // [h][m][n]

__device__ __forceinline__ ull pk2(float lo, float hi) {
    ull r; asm("mov.b64 %0, {%1, %2};" : "=l"(r) : "f"(lo), "f"(hi)); return r;
}
__device__ __forceinline__ void upk2(ull v, float& lo, float& hi) {
    asm("mov.b64 {%0, %1}, %2;" : "=f"(lo), "=f"(hi) : "l"(v));
}
__device__ __forceinline__ ull fma2(ull a, ull b, ull c) {
    ull d; asm("fma.rn.f32x2 %0, %1, %2, %3;" : "=l"(d) : "l"(a), "l"(b), "l"(c)); return d;
}

// ------------------- prep: transpose weights + gather pos bias -------------------
__global__ void prep_kernel(const float* __restrict__ qkv_w,
                            const float* __restrict__ proj_w,
                            const float* __restrict__ table,
                            const int*   __restrict__ pidx)
{
    int i = blockIdx.x * 256 + threadIdx.x;
    if (i < 3 * CDIM * CDIM) {
        int o = i / CDIM, c = i % CDIM;
        g_qkv_wt[c * (3 * CDIM) + o] = qkv_w[i];
    }
    if (i < CDIM * CDIM) {
        int o = i / CDIM, c = i % CDIM;
        g_proj_wt[c * CDIM + o] = proj_w[i];
    }
    if (i < HEADS * NTOK * NTOK) {
        int h = i / (NTOK * NTOK), r = i % (NTOK * NTOK);
        int m = r / NTOK, n = r % NTOK;
        g_pbias[i] = table[pidx[n * NTOK + m] * HEADS + h];
    }
}

// ------------------------------- main kernel -------------------------------
__global__ void __launch_bounds__(THREADS)
win_attn_kernel(const float* __restrict__ x,
                const float* __restrict__ mask,
                const float* __restrict__ proj_b,
                float* __restrict__ out,
                int nW)
{
    extern __shared__ float smem[];
    float* s_x2  = smem;                 // [50][268] dup pairs
    float* s_qkv = smem + X2_FLOATS;     // [50][388]
    float* s_msk = s_qkv + QKV_FLOATS;   // [49*49]

    const int b = blockIdx.x;
    const int t = threadIdx.x;

    // ------------- Phase 1: load x (duplicated pairs) + mask -------------
    {
        const float4* x4 = (const float4*)(x + (size_t)b * NTOK * CDIM);
        #pragma unroll 1
        for (int i = t; i < NTOK * CDIM / 4; i += THREADS) {
            float4 v = __ldg(x4 + i);
            int n  = i >> 5;
            int c4 = (i & 31) << 2;
            float* dst = s_x2 + n * X2_STRIDE + 2 * c4;
            float4 d0 = make_float4(v.x, v.x, v.y, v.y);
            float4 d1 = make_float4(v.z, v.z, v.w, v.w);
            *(float4*)(dst)     = d0;
            *(float4*)(dst + 4) = d1;
        }
        const float* mrow = mask + (size_t)(b % nW) * NTOK * NTOK;
        #pragma unroll 1
        for (int i = t; i < NTOK * NTOK; i += THREADS)
            s_msk[i] = __ldg(mrow + i);
    }
    __syncthreads();

    // ------------- Phase 2: qkv = x @ W^T, thread = (rowgroup, colquad) -------------
    // groups of rows: n0 in {0,13,25,37}, 13 rows each (overlap rows 25/37 + pad row 49 benign)
    {
        const int g2 = t / 96;
        const int cq = t % 96;
        const int n0 = g2 * 12 + (g2 ? 1 : 0) + (g2 > 1 ? (g2 - 1) * 0 : 0); // 0,13,25,37
        // (explicit: g2=0->0, 1->13, 2->25, 3->37)
        const int n0f = (g2 == 0) ? 0 : (g2 == 1 ? 13 : (g2 == 2 ? 25 : 37));

        ull acc[13][2];
        #pragma unroll
        for (int r = 0; r < 13; r++) { acc[r][0] = 0ull; acc[r][1] = 0ull; }

        const float* wbase = g_qkv_wt + 4 * cq;
        ulonglong2 w[4];
        #pragma unroll
        for (int j = 0; j < 4; j++)
            w[j] = __ldg((const ulonglong2*)(wbase + j * 384));

        #pragma unroll 1
        for (int cc = 0; cc < 32; cc++) {
            ulonglong2 wc[4];
            #pragma unroll
            for (int j = 0; j < 4; j++) wc[j] = w[j];
            if (cc < 31) {
                const float* wn = wbase + (4 * cc + 4) * 384;
                #pragma unroll
                for (int j = 0; j < 4; j++)
                    w[j] = __ldg((const ulonglong2*)(wn + j * 384));
            }
            const float* xb = s_x2 + n0f * X2_STRIDE + 8 * cc;
            #pragma unroll
            for (int r = 0; r < 13; r++) {
                const ulonglong2* xp = (const ulonglong2*)(xb + r * X2_STRIDE);
                ulonglong2 xd0 = xp[0];   // dup(c0), dup(c1)
                ulonglong2 xd1 = xp[1];   // dup(c2), dup(c3)
                acc[r][0] = fma2(xd0.x, wc[0].x, acc[r][0]);
                acc[r][1] = fma2(xd0.x, wc[0].y, acc[r][1]);
                acc[r][0] = fma2(xd0.y, wc[1].x, acc[r][0]);
                acc[r][1] = fma2(xd0.y, wc[1].y, acc[r][1]);
                acc[r][0] = fma2(xd1.x, wc[2].x, acc[r][0]);
                acc[r][1] = fma2(xd1.x, wc[2].y, acc[r][1]);
                acc[r][0] = fma2(xd1.y, wc[3].x, acc[r][0]);
                acc[r][1] = fma2(xd1.y, wc[3].y, acc[r][1]);
            }
        }
        (void)n0;
        #pragma unroll
        for (int r = 0; r < 13; r++) {
            ulonglong2 st; st.x = acc[r][0]; st.y = acc[r][1];
            *(ulonglong2*)(s_qkv + (n0f + r) * QKV_STRIDE + 4 * cq) = st;
        }
    }
    __syncthreads();

    // ------------- Phase 3: attention per (head, row) -------------
    if (t < HEADS * NTOK) {
        const int h = t / NTOK;
        const int n = t % NTOK;

        ull q2[16];
        {
            const ulonglong2* qrow = (const ulonglong2*)(s_qkv + n * QKV_STRIDE + h * HD);
            #pragma unroll
            for (int i = 0; i < 8; i++) {
                ulonglong2 v = qrow[i];
                q2[2 * i] = v.x; q2[2 * i + 1] = v.y;
            }
        }

        float p[NTOK];
        float mx = -1e30f;
        const float* pbrow = g_pbias + (size_t)h * NTOK * NTOK + n;  // [h][m][n]
        const float* mkrow = s_msk + n * NTOK;

        #pragma unroll
        for (int m = 0; m < NTOK; m++) {
            const ulonglong2* krow =
                (const ulonglong2*)(s_qkv + m * QKV_STRIDE + CDIM + h * HD);
            ull sa = 0ull, sb = 0ull;
            #pragma unroll
            for (int i = 0; i < 8; i++) {
                ulonglong2 kv = krow[i];
                sa = fma2(q2[2 * i],     kv.x, sa);
                sb = fma2(q2[2 * i + 1], kv.y, sb);
            }
            float a0, a1, b0, b1; upk2(sa, a0, a1); upk2(sb, b0, b1);
            float dot = (a0 + a1) + (b0 + b1);
            float pb = __ldg(pbrow + m * NTOK);
            float s = fmaf(dot, SCALE, pb + mkrow[m]);
            p[m] = s;
            mx = fmaxf(mx, s);
        }

        float sum = 0.f;
        #pragma unroll
        for (int m = 0; m < NTOK; m++) { p[m] = __expf(p[m] - mx); sum += p[m]; }
        float inv = 1.0f / sum;

        ull acc[16];
        #pragma unroll
        for (int i = 0; i < 16; i++) acc[i] = 0ull;
        #pragma unroll
        for (int m = 0; m < NTOK; m++) {
            ull pm2 = pk2(p[m], p[m]);
            const ulonglong2* vrow =
                (const ulonglong2*)(s_qkv + m * QKV_STRIDE + 2 * CDIM + h * HD);
            #pragma unroll
            for (int i = 0; i < 8; i++) {
                ulonglong2 vv = vrow[i];
                acc[2 * i]     = fma2(pm2, vv.x, acc[2 * i]);
                acc[2 * i + 1] = fma2(pm2, vv.y, acc[2 * i + 1]);
            }
        }

        // store duplicated pairs into s_x2 overlay (x tile is dead)
        float* orow = s_x2 + n * X2_STRIDE + 2 * (h * HD);
        #pragma unroll
        for (int i = 0; i < 16; i++) {
            float lo, hi; upk2(acc[i], lo, hi);
            lo *= inv; hi *= inv;
            ulonglong2 d;
            d.x = pk2(lo, lo);
            d.y = pk2(hi, hi);
            *(ulonglong2*)(orow + 4 * i) = d;
        }
    }
    __syncthreads();

    // ------------- Phase 4: out = o @ proj^T + b -------------
    {
        const int q = t & 31;        // col quad: cols 4q..4q+3
        const int g = t >> 5;        // warp id 0..11 -> rows g, g+12, g+24, g+36 (+48 for g==0)

        ull acc[4][2];
        #pragma unroll
        for (int r = 0; r < 4; r++) { acc[r][0] = 0ull; acc[r][1] = 0ull; }
        ull accx0 = 0ull, accx1 = 0ull;   // row 48 (g==0 only)

        const float* wbase = g_proj_wt + 4 * q;
        #pragma unroll 1
        for (int cc = 0; cc < 32; cc++) {
            ulonglong2 wc[4];
            #pragma unroll
            for (int j = 0; j < 4; j++)
                wc[j] = __ldg((const ulonglong2*)(wbase + (4 * cc + j) * CDIM));
            #pragma unroll
            for (int r = 0; r < 4; r++) {
                const ulonglong2* xp =
                    (const ulonglong2*)(s_x2 + (g + 12 * r) * X2_STRIDE + 8 * cc);
                ulonglong2 xd0 = xp[0], xd1 = xp[1];
                acc[r][0] = fma2(xd0.x, wc[0].x, acc[r][0]);
                acc[r][1] = fma2(xd0.x, wc[0].y, acc[r][1]);
                acc[r][0] = fma2(xd0.y, wc[1].x, acc[r][0]);
                acc[r][1] = fma2(xd0.y, wc[1].y, acc[r][1]);
                acc[r][0] = fma2(xd1.x, wc[2].x, acc[r][0]);
                acc[r][1] = fma2(xd1.x, wc[2].y, acc[r][1]);
                acc[r][0] = fma2(xd1.y, wc[3].x, acc[r][0]);
                acc[r][1] = fma2(xd1.y, wc[3].y, acc[r][1]);
            }
            if (g == 0) {
                const ulonglong2* xp =
                    (const ulonglong2*)(s_x2 + 48 * X2_STRIDE + 8 * cc);
                ulonglong2 xd0 = xp[0], xd1 = xp[1];
                accx0 = fma2(xd0.x, wc[0].x, accx0);
                accx1 = fma2(xd0.x, wc[0].y, accx1);
                accx0 = fma2(xd0.y, wc[1].x, accx0);
                accx1 = fma2(xd0.y, wc[1].y, accx1);
                accx0 = fma2(xd1.x, wc[2].x, accx0);
                accx1 = fma2(xd1.x, wc[2].y, accx1);
                accx0 = fma2(xd1.y, wc[3].x, accx0);
                accx1 = fma2(xd1.y, wc[3].y, accx1);
            }
        }

        float4 bias = __ldg((const float4*)(proj_b + 4 * q));
        float* obase = out + (size_t)b * NTOK * CDIM;
        #pragma unroll
        for (int r = 0; r < 4; r++) {
            int n = g + 12 * r;
            float l0, h0, l1, h1;
            upk2(acc[r][0], l0, h0); upk2(acc[r][1], l1, h1);
            float4 o4 = make_float4(l0 + bias.x, h0 + bias.y, l1 + bias.z, h1 + bias.w);
            *(float4*)(obase + n * CDIM + 4 * q) = o4;
        }
        if (g == 0) {
            float l0, h0, l1, h1;
            upk2(accx0, l0, h0); upk2(accx1, l1, h1);
            float4 o4 = make_float4(l0 + bias.x, h0 + bias.y, l1 + bias.z, h1 + bias.w);
            *(float4*)(obase + 48 * CDIM + 4 * q) = o4;
        }
    }
}

extern "C" void kernel_launch(void* const* d_in, const int* in_sizes, int n_in,
                              void* d_out, int out_size)
{
    const float* x      = (const float*)d_in[0];
    const float* qkv_w  = (const float*)d_in[1];
    const float* proj_w = (const float*)d_in[2];
    const float* proj_b = (const float*)d_in[3];
    const float* table  = (const float*)d_in[4];
    const float* mask   = (const float*)d_in[5];
    const int*   pidx   = (const int*)d_in[6];
    float* out = (float*)d_out;

    int B  = in_sizes[0] / (NTOK * CDIM);      // 8192
    int nW = in_sizes[5] / (NTOK * NTOK);      // 1024

    prep_kernel<<<(3 * CDIM * CDIM + 255) / 256, 256>>>(qkv_w, proj_w, table, pidx);

    cudaFuncSetAttribute(win_attn_kernel,
                         cudaFuncAttributeMaxDynamicSharedMemorySize, SMEM_BYTES);
    win_attn_kernel<<<B, THREADS, SMEM_BYTES>>>(x, mask, proj_b, out, nW);
}

// round 4
// speedup vs baseline: 1.1598x; 1.0026x over previous
#include <cuda_runtime.h>

#define NTOK 49
#define CDIM 128
#define HEADS 4
#define HD 32
#define THREADS 384

static constexpr float SCALE = 0.17677669529663687f; // 32^-0.5

// smem (floats):
//   s_x2  : [50][268]  x duplicated pairs (x,x) per channel; overlaid by o2 (same fmt) in phase 3/4
//   s_qkv : [50][388]  qkv activations (q:0..127, k:128..255, v:256..383)
//   s_msk : [49*49]
#define X2_STRIDE  268
#define QKV_STRIDE 388
#define X2_FLOATS  (50 * X2_STRIDE)     // 13400
#define QKV_FLOATS (50 * QKV_STRIDE)    // 19400
#define MSK_FLOATS (NTOK * NTOK)        // 2401
#define SMEM_FLOATS (X2_FLOATS + QKV_FLOATS + MSK_FLOATS)
#define SMEM_BYTES  (SMEM_FLOATS * 4)   // 140804 B

typedef unsigned long long ull;

__device__ float g_qkv_wt[CDIM * 3 * CDIM];     // [c][384]
__device__ float g_proj_wt[CDIM * CDIM];        // [c][128]
__device__ float g_pbias[HEADS * NTOK * NTOK];  // [h][m][n]

__device__ __forceinline__ ull pk2(float lo, float hi) {
    ull r; asm("mov.b64 %0, {%1, %2};" : "=l"(r) : "f"(lo), "f"(hi)); return r;
}
__device__ __forceinline__ void upk2(ull v, float& lo, float& hi) {
    asm("mov.b64 {%0, %1}, %2;" : "=f"(lo), "=f"(hi) : "l"(v));
}
__device__ __forceinline__ ull fma2(ull a, ull b, ull c) {
    ull d; asm("fma.rn.f32x2 %0, %1, %2, %3;" : "=l"(d) : "l"(a), "l"(b), "l"(c)); return d;
}

// ------------------- prep: transpose weights + gather pos bias -------------------
__global__ void prep_kernel(const float* __restrict__ qkv_w,
                            const float* __restrict__ proj_w,
                            const float* __restrict__ table,
                            const int*   __restrict__ pidx)
{
    int i = blockIdx.x * 256 + threadIdx.x;
    if (i < 3 * CDIM * CDIM) {
        int o = i / CDIM, c = i % CDIM;
        g_qkv_wt[c * (3 * CDIM) + o] = qkv_w[i];
    }
    if (i < CDIM * CDIM) {
        int o = i / CDIM, c = i % CDIM;
        g_proj_wt[c * CDIM + o] = proj_w[i];
    }
    if (i < HEADS * NTOK * NTOK) {
        int h = i / (NTOK * NTOK), r = i % (NTOK * NTOK);
        int m = r / NTOK, n = r % NTOK;
        g_pbias[i] = table[pidx[n * NTOK + m] * HEADS + h];
    }
}

// ------------------------------- main kernel -------------------------------
__global__ void __launch_bounds__(THREADS)
win_attn_kernel(const float* __restrict__ x,
                const float* __restrict__ mask,
                const float* __restrict__ proj_b,
                float* __restrict__ out,
                int nW)
{
    extern __shared__ float smem[];
    float* s_x2  = smem;                 // [50][268] dup pairs
    float* s_qkv = smem + X2_FLOATS;     // [50][388]
    float* s_msk = s_qkv + QKV_FLOATS;   // [49*49]

    const int b = blockIdx.x;
    const int t = threadIdx.x;

    // ------------- Phase 1: load x (duplicated pairs) + mask -------------
    {
        const float4* x4 = (const float4*)(x + (size_t)b * NTOK * CDIM);
        #pragma unroll 1
        for (int i = t; i < NTOK * CDIM / 4; i += THREADS) {
            float4 v = __ldg(x4 + i);
            int n  = i >> 5;
            int c4 = (i & 31) << 2;
            float* dst = s_x2 + n * X2_STRIDE + 2 * c4;
            float4 d0 = make_float4(v.x, v.x, v.y, v.y);
            float4 d1 = make_float4(v.z, v.z, v.w, v.w);
            *(float4*)(dst)     = d0;
            *(float4*)(dst + 4) = d1;
        }
        const float* mrow = mask + (size_t)(b % nW) * NTOK * NTOK;
        #pragma unroll 1
        for (int i = t; i < NTOK * NTOK; i += THREADS)
            s_msk[i] = __ldg(mrow + i);
    }
    __syncthreads();

    // ------------- Phase 2: qkv = x @ W^T, thread = (rowgroup, colquad) -------------
    // groups of rows: n0 in {0,13,25,37}, 13 rows each (overlap rows 25/37 + pad row 49 benign)
    {
        const int g2 = t / 96;
        const int cq = t % 96;
        const int n0 = g2 * 12 + (g2 ? 1 : 0) + (g2 > 1 ? (g2 - 1) * 0 : 0); // 0,13,25,37
        // (explicit: g2=0->0, 1->13, 2->25, 3->37)
        const int n0f = (g2 == 0) ? 0 : (g2 == 1 ? 13 : (g2 == 2 ? 25 : 37));

        ull acc[13][2];
        #pragma unroll
        for (int r = 0; r < 13; r++) { acc[r][0] = 0ull; acc[r][1] = 0ull; }

        const float* wbase = g_qkv_wt + 4 * cq;
        ulonglong2 w[4];
        #pragma unroll
        for (int j = 0; j < 4; j++)
            w[j] = __ldg((const ulonglong2*)(wbase + j * 384));

        #pragma unroll 1
        for (int cc = 0; cc < 32; cc++) {
            ulonglong2 wc[4];
            #pragma unroll
            for (int j = 0; j < 4; j++) wc[j] = w[j];
            if (cc < 31) {
                const float* wn = wbase + (4 * cc + 4) * 384;
                #pragma unroll
                for (int j = 0; j < 4; j++)
                    w[j] = __ldg((const ulonglong2*)(wn + j * 384));
            }
            const float* xb = s_x2 + n0f * X2_STRIDE + 8 * cc;
            #pragma unroll
            for (int r = 0; r < 13; r++) {
                const ulonglong2* xp = (const ulonglong2*)(xb + r * X2_STRIDE);
                ulonglong2 xd0 = xp[0];   // dup(c0), dup(c1)
                ulonglong2 xd1 = xp[1];   // dup(c2), dup(c3)
                acc[r][0] = fma2(xd0.x, wc[0].x, acc[r][0]);
                acc[r][1] = fma2(xd0.x, wc[0].y, acc[r][1]);
                acc[r][0] = fma2(xd0.y, wc[1].x, acc[r][0]);
                acc[r][1] = fma2(xd0.y, wc[1].y, acc[r][1]);
                acc[r][0] = fma2(xd1.x, wc[2].x, acc[r][0]);
                acc[r][1] = fma2(xd1.x, wc[2].y, acc[r][1]);
                acc[r][0] = fma2(xd1.y, wc[3].x, acc[r][0]);
                acc[r][1] = fma2(xd1.y, wc[3].y, acc[r][1]);
            }
        }
        (void)n0;
        #pragma unroll
        for (int r = 0; r < 13; r++) {
            ulonglong2 st; st.x = acc[r][0]; st.y = acc[r][1];
            *(ulonglong2*)(s_qkv + (n0f + r) * QKV_STRIDE + 4 * cq) = st;
        }
    }
    __syncthreads();

    // ------------- Phase 3: attention per (head, row) -------------
    if (t < HEADS * NTOK) {
        const int h = t / NTOK;
        const int n = t % NTOK;

        ull q2[16];
        {
            const ulonglong2* qrow = (const ulonglong2*)(s_qkv + n * QKV_STRIDE + h * HD);
            #pragma unroll
            for (int i = 0; i < 8; i++) {
                ulonglong2 v = qrow[i];
                q2[2 * i] = v.x; q2[2 * i + 1] = v.y;
            }
        }

        float p[NTOK];
        float mx = -1e30f;
        const float* pbrow = g_pbias + (size_t)h * NTOK * NTOK + n;  // [h][m][n]
        const float* mkrow = s_msk + n * NTOK;

        #pragma unroll
        for (int m = 0; m < NTOK; m++) {
            const ulonglong2* krow =
                (const ulonglong2*)(s_qkv + m * QKV_STRIDE + CDIM + h * HD);
            ull sa = 0ull, sb = 0ull;
            #pragma unroll
            for (int i = 0; i < 8; i++) {
                ulonglong2 kv = krow[i];
                sa = fma2(q2[2 * i],     kv.x, sa);
                sb = fma2(q2[2 * i + 1], kv.y, sb);
            }
            float a0, a1, b0, b1; upk2(sa, a0, a1); upk2(sb, b0, b1);
            float dot = (a0 + a1) + (b0 + b1);
            float pb = __ldg(pbrow + m * NTOK);
            float s = fmaf(dot, SCALE, pb + mkrow[m]);
            p[m] = s;
            mx = fmaxf(mx, s);
        }

        float sum = 0.f;
        #pragma unroll
        for (int m = 0; m < NTOK; m++) { p[m] = __expf(p[m] - mx); sum += p[m]; }
        float inv = 1.0f / sum;

        ull acc[16];
        #pragma unroll
        for (int i = 0; i < 16; i++) acc[i] = 0ull;
        #pragma unroll
        for (int m = 0; m < NTOK; m++) {
            ull pm2 = pk2(p[m], p[m]);
            const ulonglong2* vrow =
                (const ulonglong2*)(s_qkv + m * QKV_STRIDE + 2 * CDIM + h * HD);
            #pragma unroll
            for (int i = 0; i < 8; i++) {
                ulonglong2 vv = vrow[i];
                acc[2 * i]     = fma2(pm2, vv.x, acc[2 * i]);
                acc[2 * i + 1] = fma2(pm2, vv.y, acc[2 * i + 1]);
            }
        }

        // store duplicated pairs into s_x2 overlay (x tile is dead)
        float* orow = s_x2 + n * X2_STRIDE + 2 * (h * HD);
        #pragma unroll
        for (int i = 0; i < 16; i++) {
            float lo, hi; upk2(acc[i], lo, hi);
            lo *= inv; hi *= inv;
            ulonglong2 d;
            d.x = pk2(lo, lo);
            d.y = pk2(hi, hi);
            *(ulonglong2*)(orow + 4 * i) = d;
        }
    }
    __syncthreads();

    // ------------- Phase 4: out = o @ proj^T + b -------------
    {
        const int q = t & 31;        // col quad: cols 4q..4q+3
        const int g = t >> 5;        // warp id 0..11 -> rows g, g+12, g+24, g+36 (+48 for g==0)

        ull acc[4][2];
        #pragma unroll
        for (int r = 0; r < 4; r++) { acc[r][0] = 0ull; acc[r][1] = 0ull; }
        ull accx0 = 0ull, accx1 = 0ull;   // row 48 (g==0 only)

        const float* wbase = g_proj_wt + 4 * q;
        #pragma unroll 1
        for (int cc = 0; cc < 32; cc++) {
            ulonglong2 wc[4];
            #pragma unroll
            for (int j = 0; j < 4; j++)
                wc[j] = __ldg((const ulonglong2*)(wbase + (4 * cc + j) * CDIM));
            #pragma unroll
            for (int r = 0; r < 4; r++) {
                const ulonglong2* xp =
                    (const ulonglong2*)(s_x2 + (g + 12 * r) * X2_STRIDE + 8 * cc);
                ulonglong2 xd0 = xp[0], xd1 = xp[1];
                acc[r][0] = fma2(xd0.x, wc[0].x, acc[r][0]);
                acc[r][1] = fma2(xd0.x, wc[0].y, acc[r][1]);
                acc[r][0] = fma2(xd0.y, wc[1].x, acc[r][0]);
                acc[r][1] = fma2(xd0.y, wc[1].y, acc[r][1]);
                acc[r][0] = fma2(xd1.x, wc[2].x, acc[r][0]);
                acc[r][1] = fma2(xd1.x, wc[2].y, acc[r][1]);
                acc[r][0] = fma2(xd1.y, wc[3].x, acc[r][0]);
                acc[r][1] = fma2(xd1.y, wc[3].y, acc[r][1]);
            }
            if (g == 0) {
                const ulonglong2* xp =
                    (const ulonglong2*)(s_x2 + 48 * X2_STRIDE + 8 * cc);
                ulonglong2 xd0 = xp[0], xd1 = xp[1];
                accx0 = fma2(xd0.x, wc[0].x, accx0);
                accx1 = fma2(xd0.x, wc[0].y, accx1);
                accx0 = fma2(xd0.y, wc[1].x, accx0);
                accx1 = fma2(xd0.y, wc[1].y, accx1);
                accx0 = fma2(xd1.x, wc[2].x, accx0);
                accx1 = fma2(xd1.x, wc[2].y, accx1);
                accx0 = fma2(xd1.y, wc[3].x, accx0);
                accx1 = fma2(xd1.y, wc[3].y, accx1);
            }
        }

        float4 bias = __ldg((const float4*)(proj_b + 4 * q));
        float* obase = out + (size_t)b * NTOK * CDIM;
        #pragma unroll
        for (int r = 0; r < 4; r++) {
            int n = g + 12 * r;
            float l0, h0, l1, h1;
            upk2(acc[r][0], l0, h0); upk2(acc[r][1], l1, h1);
            float4 o4 = make_float4(l0 + bias.x, h0 + bias.y, l1 + bias.z, h1 + bias.w);
            *(float4*)(obase + n * CDIM + 4 * q) = o4;
        }
        if (g == 0) {
            float l0, h0, l1, h1;
            upk2(accx0, l0, h0); upk2(accx1, l1, h1);
            float4 o4 = make_float4(l0 + bias.x, h0 + bias.y, l1 + bias.z, h1 + bias.w);
            *(float4*)(obase + 48 * CDIM + 4 * q) = o4;
        }
    }
}

extern "C" void kernel_launch(void* const* d_in, const int* in_sizes, int n_in,
                              void* d_out, int out_size)
{
    const float* x      = (const float*)d_in[0];
    const float* qkv_w  = (const float*)d_in[1];
    const float* proj_w = (const float*)d_in[2];
    const float* proj_b = (const float*)d_in[3];
    const float* table  = (const float*)d_in[4];
    const float* mask   = (const float*)d_in[5];
    const int*   pidx   = (const int*)d_in[6];
    float* out = (float*)d_out;

    int B  = in_sizes[0] / (NTOK * CDIM);      // 8192
    int nW = in_sizes[5] / (NTOK * NTOK);      // 1024

    prep_kernel<<<(3 * CDIM * CDIM + 255) / 256, 256>>>(qkv_w, proj_w, table, pidx);

    cudaFuncSetAttribute(win_attn_kernel,
                         cudaFuncAttributeMaxDynamicSharedMemorySize, SMEM_BYTES);
    win_attn_kernel<<<B, THREADS, SMEM_BYTES>>>(x, mask, proj_b, out, nW);
}

// round 5
// speedup vs baseline: 1.2139x; 1.0466x over previous
#include <cuda_runtime.h>

#define NTOK 49
#define CDIM 128
#define HEADS 4
#define HD 32
#define THREADS 768

static constexpr float SCALE = 0.17677669529663687f; // 32^-0.5

// smem (floats):
//   s_x2  : [49][268]  x duplicated pairs (x,x); overlaid by p-scratch [49][196] then o2 dup
//   s_qkv : [49][388]  qkv activations (q:0..127, k:128..255, v:256..383)
//   s_msk : [49*49]
#define X2_STRIDE  268
#define QKV_STRIDE 388
#define X2_FLOATS  (49 * X2_STRIDE)     // 13132
#define QKV_FLOATS (49 * QKV_STRIDE)    // 19012
#define MSK_FLOATS (NTOK * NTOK)        // 2401
#define SMEM_FLOATS (X2_FLOATS + QKV_FLOATS + MSK_FLOATS)
#define SMEM_BYTES  (SMEM_FLOATS * 4)   // 138180 B

typedef unsigned long long ull;

__device__ float g_qkv_wt[CDIM * 3 * CDIM];     // [c][384]
__device__ float g_proj_wt[CDIM * CDIM];        // [c][128]
__device__ float g_pbias[HEADS * NTOK * NTOK];  // [h][m][n]

__device__ __forceinline__ ull pk2(float lo, float hi) {
    ull r; asm("mov.b64 %0, {%1, %2};" : "=l"(r) : "f"(lo), "f"(hi)); return r;
}
__device__ __forceinline__ void upk2(ull v, float& lo, float& hi) {
    asm("mov.b64 {%0, %1}, %2;" : "=f"(lo), "=f"(hi) : "l"(v));
}
__device__ __forceinline__ ull fma2(ull a, ull b, ull c) {
    ull d; asm("fma.rn.f32x2 %0, %1, %2, %3;" : "=l"(d) : "l"(a), "l"(b), "l"(c)); return d;
}

// ------------------- prep: transpose weights + gather pos bias -------------------
__global__ void prep_kernel(const float* __restrict__ qkv_w,
                            const float* __restrict__ proj_w,
                            const float* __restrict__ table,
                            const int*   __restrict__ pidx)
{
    int i = blockIdx.x * 256 + threadIdx.x;
    if (i < 3 * CDIM * CDIM) {
        int o = i / CDIM, c = i % CDIM;
        g_qkv_wt[c * (3 * CDIM) + o] = qkv_w[i];
    }
    if (i < CDIM * CDIM) {
        int o = i / CDIM, c = i % CDIM;
        g_proj_wt[c * CDIM + o] = proj_w[i];
    }
    if (i < HEADS * NTOK * NTOK) {
        int h = i / (NTOK * NTOK), r = i % (NTOK * NTOK);
        int m = r / NTOK, n = r % NTOK;
        g_pbias[i] = table[pidx[n * NTOK + m] * HEADS + h];
    }
}

// ------------------------------- main kernel -------------------------------
__global__ void __launch_bounds__(THREADS, 1)
win_attn_kernel(const float* __restrict__ x,
                const float* __restrict__ mask,
                const float* __restrict__ proj_b,
                float* __restrict__ out,
                int nW)
{
    extern __shared__ float smem[];
    float* s_x2  = smem;                 // [49][268] dup pairs / p-scratch / o2
    float* s_qkv = smem + X2_FLOATS;     // [49][388]
    float* s_msk = s_qkv + QKV_FLOATS;   // [49*49]

    const int b = blockIdx.x;
    const int t = threadIdx.x;

    // ------------- Phase 1: load x (duplicated pairs) + mask -------------
    {
        const float4* x4 = (const float4*)(x + (size_t)b * NTOK * CDIM);
        #pragma unroll 1
        for (int i = t; i < NTOK * CDIM / 4; i += THREADS) {
            float4 v = __ldg(x4 + i);
            int n  = i >> 5;
            int c4 = (i & 31) << 2;
            float* dst = s_x2 + n * X2_STRIDE + 2 * c4;
            *(float4*)(dst)     = make_float4(v.x, v.x, v.y, v.y);
            *(float4*)(dst + 4) = make_float4(v.z, v.z, v.w, v.w);
        }
        const float* mrow = mask + (size_t)(b % nW) * NTOK * NTOK;
        #pragma unroll 1
        for (int i = t; i < NTOK * NTOK; i += THREADS)
            s_msk[i] = __ldg(mrow + i);
    }
    __syncthreads();

    // ------------- Phase 2: qkv = x @ W^T -------------
    // 8 row-groups x 96 col-quads. g=0: rows 0..6 (7), g>=1: rows 6g+1..6g+6 (6).
    {
        const int g2   = t / 96;
        const int cq   = t % 96;
        const int base = (g2 == 0) ? 0 : (6 * g2 + 1);

        ull acc[6][2];
        #pragma unroll
        for (int r = 0; r < 6; r++) { acc[r][0] = 0ull; acc[r][1] = 0ull; }
        ull acc6[2] = {0ull, 0ull};          // extra row 6 for g2==0

        const float* wbase = g_qkv_wt + 4 * cq;
        #pragma unroll 1
        for (int cc = 0; cc < 32; cc++) {
            ulonglong2 wc[4];
            #pragma unroll
            for (int j = 0; j < 4; j++)
                wc[j] = __ldg((const ulonglong2*)(wbase + (4 * cc + j) * 384));
            const float* xb = s_x2 + base * X2_STRIDE + 8 * cc;
            #pragma unroll
            for (int r = 0; r < 6; r++) {
                const ulonglong2* xp = (const ulonglong2*)(xb + r * X2_STRIDE);
                ulonglong2 xd0 = xp[0];   // dup(c0), dup(c1)
                ulonglong2 xd1 = xp[1];   // dup(c2), dup(c3)
                acc[r][0] = fma2(xd0.x, wc[0].x, acc[r][0]);
                acc[r][1] = fma2(xd0.x, wc[0].y, acc[r][1]);
                acc[r][0] = fma2(xd0.y, wc[1].x, acc[r][0]);
                acc[r][1] = fma2(xd0.y, wc[1].y, acc[r][1]);
                acc[r][0] = fma2(xd1.x, wc[2].x, acc[r][0]);
                acc[r][1] = fma2(xd1.x, wc[2].y, acc[r][1]);
                acc[r][0] = fma2(xd1.y, wc[3].x, acc[r][0]);
                acc[r][1] = fma2(xd1.y, wc[3].y, acc[r][1]);
            }
            if (g2 == 0) {   // warp-uniform branch (96 = 3 warps per group)
                const ulonglong2* xp = (const ulonglong2*)(xb + 6 * X2_STRIDE);
                ulonglong2 xd0 = xp[0], xd1 = xp[1];
                acc6[0] = fma2(xd0.x, wc[0].x, acc6[0]);
                acc6[1] = fma2(xd0.x, wc[0].y, acc6[1]);
                acc6[0] = fma2(xd0.y, wc[1].x, acc6[0]);
                acc6[1] = fma2(xd0.y, wc[1].y, acc6[1]);
                acc6[0] = fma2(xd1.x, wc[2].x, acc6[0]);
                acc6[1] = fma2(xd1.x, wc[2].y, acc6[1]);
                acc6[0] = fma2(xd1.y, wc[3].x, acc6[0]);
                acc6[1] = fma2(xd1.y, wc[3].y, acc6[1]);
            }
        }
        #pragma unroll
        for (int r = 0; r < 6; r++) {
            ulonglong2 st; st.x = acc[r][0]; st.y = acc[r][1];
            *(ulonglong2*)(s_qkv + (base + r) * QKV_STRIDE + 4 * cq) = st;
        }
        if (g2 == 0) {
            ulonglong2 st; st.x = acc6[0]; st.y = acc6[1];
            *(ulonglong2*)(s_qkv + 6 * QKV_STRIDE + 4 * cq) = st;
        }
    }
    __syncthreads();

    // ------------- Phase 3: attention per (head, row); logits in smem -------------
    ull oacc[16];
    float inv = 0.f;
    int h = 0, n = 0;
    if (t < HEADS * NTOK) {
        h = t / NTOK;
        n = t % NTOK;

        // pass A: logits -> p-scratch (overlay on dead x tile), track max
        {
            ull q2[16];
            const ulonglong2* qrow = (const ulonglong2*)(s_qkv + n * QKV_STRIDE + h * HD);
            #pragma unroll
            for (int i = 0; i < 8; i++) {
                ulonglong2 v = qrow[i];
                q2[2 * i] = v.x; q2[2 * i + 1] = v.y;
            }
            float mx = -1e30f;
            const float* pbrow = g_pbias + h * (NTOK * NTOK) + n;   // [h][m][n]
            const float* mkrow = s_msk + n * NTOK;
            float* pcol = s_x2 + t;                                 // stride 196 over m
            #pragma unroll
            for (int m = 0; m < NTOK; m++) {
                const ulonglong2* krow =
                    (const ulonglong2*)(s_qkv + m * QKV_STRIDE + CDIM + h * HD);
                ull sa = 0ull, sb = 0ull;
                #pragma unroll
                for (int i = 0; i < 8; i++) {
                    ulonglong2 kv = krow[i];
                    sa = fma2(q2[2 * i],     kv.x, sa);
                    sb = fma2(q2[2 * i + 1], kv.y, sb);
                }
                float a0, a1, b0, b1; upk2(sa, a0, a1); upk2(sb, b0, b1);
                float dot = (a0 + a1) + (b0 + b1);
                float s = fmaf(dot, SCALE, __ldg(pbrow + m * NTOK) + mkrow[m]);
                pcol[m * 196] = s;
                mx = fmaxf(mx, s);
            }
            // pass B: exp + PV accumulate (q2 dead -> regs reused for oacc)
            #pragma unroll
            for (int i = 0; i < 16; i++) oacc[i] = 0ull;
            float sum = 0.f;
            #pragma unroll
            for (int m = 0; m < NTOK; m++) {
                float e = __expf(pcol[m * 196] - mx);
                sum += e;
                ull e2 = pk2(e, e);
                const ulonglong2* vrow =
                    (const ulonglong2*)(s_qkv + m * QKV_STRIDE + 2 * CDIM + h * HD);
                #pragma unroll
                for (int i = 0; i < 8; i++) {
                    ulonglong2 vv = vrow[i];
                    oacc[2 * i]     = fma2(e2, vv.x, oacc[2 * i]);
                    oacc[2 * i + 1] = fma2(e2, vv.y, oacc[2 * i + 1]);
                }
            }
            inv = 1.0f / sum;
        }
    }
    __syncthreads();   // all p-scratch reads done before o overlay writes

    if (t < HEADS * NTOK) {
        float* orow = s_x2 + n * X2_STRIDE + 2 * (h * HD);   // dup format for phase 4
        #pragma unroll
        for (int i = 0; i < 16; i++) {
            float lo, hi; upk2(oacc[i], lo, hi);
            lo *= inv; hi *= inv;
            ulonglong2 d; d.x = pk2(lo, lo); d.y = pk2(hi, hi);
            *(ulonglong2*)(orow + 4 * i) = d;
        }
    }
    __syncthreads();

    // ------------- Phase 4: out = o @ proj^T + b -------------
    {
        const int q = t & 31;        // col quad: cols 4q..4q+3
        const int g = t >> 5;        // warp id 0..23 -> rows g, g+24 (+48 for g==0)

        ull acc[2][2];
        acc[0][0] = acc[0][1] = acc[1][0] = acc[1][1] = 0ull;
        ull accx0 = 0ull, accx1 = 0ull;   // row 48 (g==0 only)

        const float* wbase = g_proj_wt + 4 * q;
        #pragma unroll 1
        for (int cc = 0; cc < 32; cc++) {
            ulonglong2 wc[4];
            #pragma unroll
            for (int j = 0; j < 4; j++)
                wc[j] = __ldg((const ulonglong2*)(wbase + (4 * cc + j) * CDIM));
            #pragma unroll
            for (int r = 0; r < 2; r++) {
                const ulonglong2* xp =
                    (const ulonglong2*)(s_x2 + (g + 24 * r) * X2_STRIDE + 8 * cc);
                ulonglong2 xd0 = xp[0], xd1 = xp[1];
                acc[r][0] = fma2(xd0.x, wc[0].x, acc[r][0]);
                acc[r][1] = fma2(xd0.x, wc[0].y, acc[r][1]);
                acc[r][0] = fma2(xd0.y, wc[1].x, acc[r][0]);
                acc[r][1] = fma2(xd0.y, wc[1].y, acc[r][1]);
                acc[r][0] = fma2(xd1.x, wc[2].x, acc[r][0]);
                acc[r][1] = fma2(xd1.x, wc[2].y, acc[r][1]);
                acc[r][0] = fma2(xd1.y, wc[3].x, acc[r][0]);
                acc[r][1] = fma2(xd1.y, wc[3].y, acc[r][1]);
            }
            if (g == 0) {
                const ulonglong2* xp =
                    (const ulonglong2*)(s_x2 + 48 * X2_STRIDE + 8 * cc);
                ulonglong2 xd0 = xp[0], xd1 = xp[1];
                accx0 = fma2(xd0.x, wc[0].x, accx0);
                accx1 = fma2(xd0.x, wc[0].y, accx1);
                accx0 = fma2(xd0.y, wc[1].x, accx0);
                accx1 = fma2(xd0.y, wc[1].y, accx1);
                accx0 = fma2(xd1.x, wc[2].x, accx0);
                accx1 = fma2(xd1.x, wc[2].y, accx1);
                accx0 = fma2(xd1.y, wc[3].x, accx0);
                accx1 = fma2(xd1.y, wc[3].y, accx1);
            }
        }

        float4 bias = __ldg((const float4*)(proj_b + 4 * q));
        float* obase = out + (size_t)b * NTOK * CDIM;
        #pragma unroll
        for (int r = 0; r < 2; r++) {
            int nn = g + 24 * r;
            float l0, h0, l1, h1;
            upk2(acc[r][0], l0, h0); upk2(acc[r][1], l1, h1);
            *(float4*)(obase + nn * CDIM + 4 * q) =
                make_float4(l0 + bias.x, h0 + bias.y, l1 + bias.z, h1 + bias.w);
        }
        if (g == 0) {
            float l0, h0, l1, h1;
            upk2(accx0, l0, h0); upk2(accx1, l1, h1);
            *(float4*)(obase + 48 * CDIM + 4 * q) =
                make_float4(l0 + bias.x, h0 + bias.y, l1 + bias.z, h1 + bias.w);
        }
    }
}

extern "C" void kernel_launch(void* const* d_in, const int* in_sizes, int n_in,
                              void* d_out, int out_size)
{
    const float* x      = (const float*)d_in[0];
    const float* qkv_w  = (const float*)d_in[1];
    const float* proj_w = (const float*)d_in[2];
    const float* proj_b = (const float*)d_in[3];
    const float* table  = (const float*)d_in[4];
    const float* mask   = (const float*)d_in[5];
    const int*   pidx   = (const int*)d_in[6];
    float* out = (float*)d_out;

    int B  = in_sizes[0] / (NTOK * CDIM);      // 8192
    int nW = in_sizes[5] / (NTOK * NTOK);      // 1024

    prep_kernel<<<(3 * CDIM * CDIM + 255) / 256, 256>>>(qkv_w, proj_w, table, pidx);

    cudaFuncSetAttribute(win_attn_kernel,
                         cudaFuncAttributeMaxDynamicSharedMemorySize, SMEM_BYTES);
    win_attn_kernel<<<B, THREADS, SMEM_BYTES>>>(x, mask, proj_b, out, nW);
}

// round 7
// speedup vs baseline: 1.8178x; 1.4975x over previous
#include <cuda_runtime.h>
#include <cuda_bf16.h>
#include <cstdint>

#define NTOK 49
#define CDIM 128
#define HEADS 4
#define HD 32
#define THREADS 768

static constexpr float SCALE = 0.17677669529663687f; // 32^-0.5

typedef unsigned long long ull;
typedef unsigned int u32;
typedef unsigned short u16;

// ---- smem byte offsets ----
#define OFF_AH   0u        // A-fragment tile hi: 64 rows x 128 k bf16 = 16KB
#define OFF_AL   16384u    // A-fragment tile lo: 16KB
#define OFF_WH   32768u    // staged W fragments hi: 32KB (16 n-tiles x 8 k-chunks x 256B)
#define OFF_WL   65536u    // staged W fragments lo: 32KB   (WH/WL double as p-scratch in phase 3)
#define OFF_QKV  98304u    // fp32 qkv [49][404] = 79184B
#define OFF_MASK 177488u   // 49*49 fp32 = 9604B
#define SMEM_BYTES 187136
#define QKV_STR  404

// ---- device globals: fragment-ordered bf16 hi/lo weights + gathered pos bias ----
__device__ u32 g_wq_hi[48 * 8 * 32 * 2];   // 96KB: 48 n-tiles (384 cols), nt-major
__device__ u32 g_wq_lo[48 * 8 * 32 * 2];
__device__ u32 g_wp_hi[16 * 8 * 32 * 2];   // 32KB
__device__ u32 g_wp_lo[16 * 8 * 32 * 2];
__device__ float g_pbias[HEADS * NTOK * NTOK];

// ============================ helpers ============================
__device__ __forceinline__ ull pk2(float lo, float hi) {
    ull r; asm("mov.b64 %0, {%1, %2};" : "=l"(r) : "f"(lo), "f"(hi)); return r;
}
__device__ __forceinline__ void upk2(ull v, float& lo, float& hi) {
    asm("mov.b64 {%0, %1}, %2;" : "=f"(lo), "=f"(hi) : "l"(v));
}
__device__ __forceinline__ ull fma2(ull a, ull b, ull c) {
    ull d; asm("fma.rn.f32x2 %0, %1, %2, %3;" : "=l"(d) : "l"(a), "l"(b), "l"(c)); return d;
}
__device__ __forceinline__ u32 bf2(float a, float b) {
    __nv_bfloat162 h = __floats2bfloat162_rn(a, b);
    return *reinterpret_cast<u32*>(&h);
}
// A-fragment u32 index for element pair (row, col) with col even, 64x128 tile
__device__ __forceinline__ int a_idx(int row, int col) {
    int mt = row >> 4, rlo = row & 15, kc = col >> 4, kk = col & 15;
    int l = (rlo & 7) * 4 + ((kk & 7) >> 1);
    int reg = ((rlo >> 3) & 1) + (((kk >> 3) & 1) << 1);
    return ((mt * 8 + kc) * 32 + l) * 4 + reg;
}
// m16n8k16 row.col f32.bf16.bf16.f32
__device__ __forceinline__ void mma16816(float c[4], const uint4& a, const uint2& b) {
    asm volatile(
        "mma.sync.aligned.m16n8k16.row.col.f32.bf16.bf16.f32 "
        "{%0,%1,%2,%3}, {%4,%5,%6,%7}, {%8,%9}, {%0,%1,%2,%3};"
        : "+f"(c[0]), "+f"(c[1]), "+f"(c[2]), "+f"(c[3])
        : "r"(a.x), "r"(a.y), "r"(a.z), "r"(a.w), "r"(b.x), "r"(b.y));
}

// ================= prep: weights -> bf16 hi/lo fragment order; pos bias gather =================
__global__ void prep_kernel(const float* __restrict__ qkv_w,
                            const float* __restrict__ proj_w,
                            const float* __restrict__ table,
                            const int*   __restrict__ pidx)
{
    int i = blockIdx.x * 256 + threadIdx.x;
    if (i < 3 * CDIM * CDIM) {
        int o = i / CDIM, c = i % CDIM;
        float w = qkv_w[i];
        __nv_bfloat16 h = __float2bfloat16(w);
        float hf = __bfloat162float(h);
        int nt = o >> 3, g = o & 7, kc = c >> 4, kk = c & 15;
        int l = g * 4 + ((kk & 7) >> 1);
        int reg = (kk >> 3) & 1;
        int u16idx = (((nt * 8 + kc) * 32 + l) * 2 + reg) * 2 + (kk & 1);
        ((u16*)g_wq_hi)[u16idx] = *(u16*)&h;
        __nv_bfloat16 lo = __float2bfloat16(w - hf);
        ((u16*)g_wq_lo)[u16idx] = *(u16*)&lo;
    }
    if (i < CDIM * CDIM) {
        int o = i / CDIM, c = i % CDIM;
        float w = proj_w[i];
        __nv_bfloat16 h = __float2bfloat16(w);
        float hf = __bfloat162float(h);
        int nt = o >> 3, g = o & 7, kc = c >> 4, kk = c & 15;
        int l = g * 4 + ((kk & 7) >> 1);
        int reg = (kk >> 3) & 1;
        int u16idx = (((nt * 8 + kc) * 32 + l) * 2 + reg) * 2 + (kk & 1);
        ((u16*)g_wp_hi)[u16idx] = *(u16*)&h;
        __nv_bfloat16 lo = __float2bfloat16(w - hf);
        ((u16*)g_wp_lo)[u16idx] = *(u16*)&lo;
    }
    if (i < HEADS * NTOK * NTOK) {
        int h = i / (NTOK * NTOK), r = i % (NTOK * NTOK);
        int m = r / NTOK, n = r % NTOK;
        g_pbias[i] = table[pidx[n * NTOK + m] * HEADS + h];
    }
}

// ================================ main kernel ================================
__global__ void __launch_bounds__(THREADS, 1)
win_attn_kernel(const float* __restrict__ x,
                const float* __restrict__ mask,
                const float* __restrict__ proj_b,
                float* __restrict__ out,
                int nW)
{
    extern __shared__ char smem[];
    const int b = blockIdx.x;
    const int t = threadIdx.x;
    const int wid = t >> 5;
    const int lane = t & 31;

    u32* sAh = (u32*)(smem + OFF_AH);
    u32* sAl = (u32*)(smem + OFF_AL);
    u32* sWh = (u32*)(smem + OFF_WH);
    u32* sWl = (u32*)(smem + OFF_WL);
    float* s_qkv  = (float*)(smem + OFF_QKV);
    float* s_mask = (float*)(smem + OFF_MASK);

    // ---- Phase 0: zero A-fragment region (padding rows 49-63 must be 0) ----
    {
        uint4* z = (uint4*)(smem + OFF_AH);
        #pragma unroll 1
        for (int i = t; i < 2048; i += THREADS)
            z[i] = make_uint4(0, 0, 0, 0);
    }
    __syncthreads();

    // ---- Phase 1: x -> A-fragments (hi/lo); mask -> smem; stage Wq chunk 0 ----
    {
        const float4* x4 = (const float4*)(x + (size_t)b * NTOK * CDIM);
        #pragma unroll 1
        for (int i = t; i < NTOK * CDIM / 4; i += THREADS) {
            float4 v = __ldg(x4 + i);
            int n = i >> 5, c4 = (i & 31) << 2;
            float h0 = __bfloat162float(__float2bfloat16(v.x));
            float h1 = __bfloat162float(__float2bfloat16(v.y));
            float h2 = __bfloat162float(__float2bfloat16(v.z));
            float h3 = __bfloat162float(__float2bfloat16(v.w));
            int i0 = a_idx(n, c4);      // pair (c4, c4+1)
            int i1 = i0 + 4;            // pair (c4+2, c4+3): l+1, same reg
            sAh[i0] = bf2(v.x, v.y);
            sAh[i1] = bf2(v.z, v.w);
            sAl[i0] = bf2(v.x - h0, v.y - h1);
            sAl[i1] = bf2(v.z - h2, v.w - h3);
        }
        const float* mrow = mask + (size_t)(b % nW) * NTOK * NTOK;
        #pragma unroll 1
        for (int i = t; i < NTOK * NTOK; i += THREADS)
            s_mask[i] = __ldg(mrow + i);
        // stage W chunk 0
        uint4* dh = (uint4*)sWh; uint4* dl = (uint4*)sWl;
        const uint4* gh = (const uint4*)g_wq_hi;
        const uint4* gl = (const uint4*)g_wq_lo;
        #pragma unroll 1
        for (int i = t; i < 2048; i += THREADS) {
            dh[i] = __ldg(gh + i);
            dl[i] = __ldg(gl + i);
        }
    }
    __syncthreads();

    // ---- GEMM1: qkv = x @ Wqkv^T, 3 chunks of 128 cols, bf16x3 mma ----
    const int mt  = wid & 3;       // m-tile: rows mt*16..mt*16+15
    const int ntg = wid >> 2;      // 0..5
    const int nnt = (ntg < 4) ? 3 : 2;   // n-tiles: ntg, ntg+6, ntg+12(<16)

    #pragma unroll 1
    for (int ch = 0; ch < 3; ch++) {
        float C[3][4];
        #pragma unroll
        for (int j = 0; j < 3; j++)
            C[j][0] = C[j][1] = C[j][2] = C[j][3] = 0.f;

        #pragma unroll
        for (int kc = 0; kc < 8; kc++) {
            uint4 ah = *(const uint4*)(sAh + ((mt * 8 + kc) * 32 + lane) * 4);
            uint4 al = *(const uint4*)(sAl + ((mt * 8 + kc) * 32 + lane) * 4);
            #pragma unroll
            for (int j = 0; j < 3; j++) {
                if (j < nnt) {
                    int nt = ntg + 6 * j;
                    uint2 bh = *(const uint2*)(sWh + ((nt * 8 + kc) * 32 + lane) * 2);
                    uint2 bl = *(const uint2*)(sWl + ((nt * 8 + kc) * 32 + lane) * 2);
                    mma16816(C[j], ah, bh);
                    mma16816(C[j], ah, bl);
                    mma16816(C[j], al, bh);
                }
            }
        }
        // store C -> s_qkv fp32
        {
            int g = lane >> 2, tid4 = lane & 3;
            int row0 = mt * 16 + g;
            #pragma unroll
            for (int j = 0; j < 3; j++) {
                if (j < nnt) {
                    int col = ch * 128 + (ntg + 6 * j) * 8 + 2 * tid4;
                    if (row0 < NTOK)
                        *(float2*)(s_qkv + row0 * QKV_STR + col) = make_float2(C[j][0], C[j][1]);
                    if (row0 + 8 < NTOK)
                        *(float2*)(s_qkv + (row0 + 8) * QKV_STR + col) = make_float2(C[j][2], C[j][3]);
                }
            }
        }
        __syncthreads();
        if (ch < 2) {
            uint4* dh = (uint4*)sWh; uint4* dl = (uint4*)sWl;
            const uint4* gh = (const uint4*)(g_wq_hi + (ch + 1) * 8192);
            const uint4* gl = (const uint4*)(g_wq_lo + (ch + 1) * 8192);
            #pragma unroll 1
            for (int i = t; i < 2048; i += THREADS) {
                dh[i] = __ldg(gh + i);
                dl[i] = __ldg(gl + i);
            }
            __syncthreads();
        }
    }

    // ---- Phase 3: scalar attention per (head, row); logits in W-region scratch ----
    ull oacc[16];
    float inv = 0.f;
    int hh = 0, nn = 0;
    if (t < HEADS * NTOK) {
        hh = t / NTOK;
        nn = t % NTOK;

        ull q2[16];
        const ulonglong2* qrow = (const ulonglong2*)(s_qkv + nn * QKV_STR + hh * HD);
        #pragma unroll
        for (int i = 0; i < 8; i++) {
            ulonglong2 v = qrow[i];
            q2[2 * i] = v.x; q2[2 * i + 1] = v.y;
        }
        float mx = -1e30f;
        const float* pbrow = g_pbias + hh * (NTOK * NTOK) + nn;
        const float* mkrow = s_mask + nn * NTOK;
        float* pcol = (float*)(smem + OFF_WH) + t;     // 196-stride scratch (W region free)

        #pragma unroll
        for (int m = 0; m < NTOK; m++) {
            const ulonglong2* krow =
                (const ulonglong2*)(s_qkv + m * QKV_STR + CDIM + hh * HD);
            ull sa = 0ull, sb = 0ull;
            #pragma unroll
            for (int i = 0; i < 8; i++) {
                ulonglong2 kv = krow[i];
                sa = fma2(q2[2 * i],     kv.x, sa);
                sb = fma2(q2[2 * i + 1], kv.y, sb);
            }
            float a0, a1, b0, b1; upk2(sa, a0, a1); upk2(sb, b0, b1);
            float dot = (a0 + a1) + (b0 + b1);
            float s = fmaf(dot, SCALE, __ldg(pbrow + m * NTOK) + mkrow[m]);
            pcol[m * 196] = s;
            mx = fmaxf(mx, s);
        }
        #pragma unroll
        for (int i = 0; i < 16; i++) oacc[i] = 0ull;
        float sum = 0.f;
        #pragma unroll
        for (int m = 0; m < NTOK; m++) {
            float e = __expf(pcol[m * 196] - mx);
            sum += e;
            ull e2 = pk2(e, e);
            const ulonglong2* vrow =
                (const ulonglong2*)(s_qkv + m * QKV_STR + 2 * CDIM + hh * HD);
            #pragma unroll
            for (int i = 0; i < 8; i++) {
                ulonglong2 vv = vrow[i];
                oacc[2 * i]     = fma2(e2, vv.x, oacc[2 * i]);
                oacc[2 * i + 1] = fma2(e2, vv.y, oacc[2 * i + 1]);
            }
        }
        inv = 1.0f / sum;
    }
    __syncthreads();   // p-scratch reads done; x-fragments dead

    // write o -> A-fragments (hi/lo), rows 49-63 keep zeros from phase 0
    if (t < HEADS * NTOK) {
        #pragma unroll
        for (int i = 0; i < 16; i++) {
            float v0, v1; upk2(oacc[i], v0, v1);
            v0 *= inv; v1 *= inv;
            float h0 = __bfloat162float(__float2bfloat16(v0));
            float h1 = __bfloat162float(__float2bfloat16(v1));
            int c = hh * HD + 2 * i;
            int idx = a_idx(nn, c);
            sAh[idx] = bf2(v0, v1);
            sAl[idx] = bf2(v0 - h0, v1 - h1);
        }
    }
    __syncthreads();   // o frags + scratch reads done before Wp staging

    // ---- stage Wproj fragments ----
    {
        uint4* dh = (uint4*)sWh; uint4* dl = (uint4*)sWl;
        const uint4* gh = (const uint4*)g_wp_hi;
        const uint4* gl = (const uint4*)g_wp_lo;
        #pragma unroll 1
        for (int i = t; i < 2048; i += THREADS) {
            dh[i] = __ldg(gh + i);
            dl[i] = __ldg(gl + i);
        }
    }
    __syncthreads();

    // ---- GEMM2: out = o @ Wproj^T + bias, direct global store ----
    {
        float C[3][4];
        #pragma unroll
        for (int j = 0; j < 3; j++)
            C[j][0] = C[j][1] = C[j][2] = C[j][3] = 0.f;

        #pragma unroll
        for (int kc = 0; kc < 8; kc++) {
            uint4 ah = *(const uint4*)(sAh + ((mt * 8 + kc) * 32 + lane) * 4);
            uint4 al = *(const uint4*)(sAl + ((mt * 8 + kc) * 32 + lane) * 4);
            #pragma unroll
            for (int j = 0; j < 3; j++) {
                if (j < nnt) {
                    int nt = ntg + 6 * j;
                    uint2 bh = *(const uint2*)(sWh + ((nt * 8 + kc) * 32 + lane) * 2);
                    uint2 bl = *(const uint2*)(sWl + ((nt * 8 + kc) * 32 + lane) * 2);
                    mma16816(C[j], ah, bh);
                    mma16816(C[j], ah, bl);
                    mma16816(C[j], al, bh);
                }
            }
        }
        int g = lane >> 2, tid4 = lane & 3;
        int row0 = mt * 16 + g;
        float* ob = out + (size_t)b * NTOK * CDIM;
        #pragma unroll
        for (int j = 0; j < 3; j++) {
            if (j < nnt) {
                int col = (ntg + 6 * j) * 8 + 2 * tid4;
                float2 bias = __ldg((const float2*)(proj_b + col));
                if (row0 < NTOK)
                    *(float2*)(ob + row0 * CDIM + col) =
                        make_float2(C[j][0] + bias.x, C[j][1] + bias.y);
                if (row0 + 8 < NTOK)
                    *(float2*)(ob + (row0 + 8) * CDIM + col) =
                        make_float2(C[j][2] + bias.x, C[j][3] + bias.y);
            }
        }
    }
}

extern "C" void kernel_launch(void* const* d_in, const int* in_sizes, int n_in,
                              void* d_out, int out_size)
{
    const float* x      = (const float*)d_in[0];
    const float* qkv_w  = (const float*)d_in[1];
    const float* proj_w = (const float*)d_in[2];
    const float* proj_b = (const float*)d_in[3];
    const float* table  = (const float*)d_in[4];
    const float* mask   = (const float*)d_in[5];
    const int*   pidx   = (const int*)d_in[6];
    float* out = (float*)d_out;

    int B  = in_sizes[0] / (NTOK * CDIM);      // 8192
    int nW = in_sizes[5] / (NTOK * NTOK);      // 1024

    prep_kernel<<<(3 * CDIM * CDIM + 255) / 256, 256>>>(qkv_w, proj_w, table, pidx);

    cudaFuncSetAttribute(win_attn_kernel,
                         cudaFuncAttributeMaxDynamicSharedMemorySize, SMEM_BYTES);
    win_attn_kernel<<<B, THREADS, SMEM_BYTES>>>(x, mask, proj_b, out, nW);
}

// round 8
// speedup vs baseline: 2.0759x; 1.1420x over previous
#include <cuda_runtime.h>
#include <cuda_bf16.h>
#include <cstdint>

#define NTOK 49
#define CDIM 128
#define HEADS 4
#define HD 32
#define THREADS 768

static constexpr float SCALE = 0.17677669529663687f; // 32^-0.5

typedef unsigned long long ull;
typedef unsigned int u32;
typedef unsigned short u16;

// ---- smem byte offsets ----
#define OFF_AH   0u         // A-fragment tile hi: 64 rows x 128 k bf16 = 16KB
#define OFF_AL   16384u     // A-fragment tile lo: 16KB
#define OFF_QKV  32768u     // fp32 qkv [49][404] = 79184B
#define OFF_MASK 111952u    // 49*49 fp32 = 9604B
#define OFF_P    121568u    // p-scratch [49][196] fp32 = 38416B
#define SMEM_BYTES 160000
#define QKV_STR  404

// ---- device globals: fragment-ordered bf16 hi/lo weights + gathered pos bias ----
__device__ u32 g_wq_hi[48 * 8 * 32 * 2];   // [nt][kc][lane][reg] u32; nt 0-47 (3 chunks x 16)
__device__ u32 g_wq_lo[48 * 8 * 32 * 2];
__device__ u32 g_wp_hi[16 * 8 * 32 * 2];
__device__ u32 g_wp_lo[16 * 8 * 32 * 2];
__device__ float g_pbias[HEADS * NTOK * NTOK];

// ============================ helpers ============================
__device__ __forceinline__ ull pk2(float lo, float hi) {
    ull r; asm("mov.b64 %0, {%1, %2};" : "=l"(r) : "f"(lo), "f"(hi)); return r;
}
__device__ __forceinline__ void upk2(ull v, float& lo, float& hi) {
    asm("mov.b64 {%0, %1}, %2;" : "=f"(lo), "=f"(hi) : "l"(v));
}
__device__ __forceinline__ ull fma2(ull a, ull b, ull c) {
    ull d; asm("fma.rn.f32x2 %0, %1, %2, %3;" : "=l"(d) : "l"(a), "l"(b), "l"(c)); return d;
}
__device__ __forceinline__ u32 bf2(float a, float b) {
    __nv_bfloat162 h = __floats2bfloat162_rn(a, b);
    return *reinterpret_cast<u32*>(&h);
}
// A-fragment u32 index for element pair (row, col) with col even, 64x128 tile
__device__ __forceinline__ int a_idx(int row, int col) {
    int mt = row >> 4, rlo = row & 15, kc = col >> 4, kk = col & 15;
    int l = (rlo & 7) * 4 + ((kk & 7) >> 1);
    int reg = ((rlo >> 3) & 1) + (((kk >> 3) & 1) << 1);
    return ((mt * 8 + kc) * 32 + l) * 4 + reg;
}
__device__ __forceinline__ void mma16816(float c[4], const uint4& a, const uint2& b) {
    asm volatile(
        "mma.sync.aligned.m16n8k16.row.col.f32.bf16.bf16.f32 "
        "{%0,%1,%2,%3}, {%4,%5,%6,%7}, {%8,%9}, {%0,%1,%2,%3};"
        : "+f"(c[0]), "+f"(c[1]), "+f"(c[2]), "+f"(c[3])
        : "r"(a.x), "r"(a.y), "r"(a.z), "r"(a.w), "r"(b.x), "r"(b.y));
}

// ================= prep: weights -> bf16 hi/lo fragment order; pos bias gather =================
__global__ void prep_kernel(const float* __restrict__ qkv_w,
                            const float* __restrict__ proj_w,
                            const float* __restrict__ table,
                            const int*   __restrict__ pidx)
{
    int i = blockIdx.x * 256 + threadIdx.x;
    if (i < 3 * CDIM * CDIM) {
        int o = i / CDIM, c = i % CDIM;
        float w = qkv_w[i];
        __nv_bfloat16 h = __float2bfloat16(w);
        float hf = __bfloat162float(h);
        int nt = o >> 3, g = o & 7, kc = c >> 4, kk = c & 15;
        int l = g * 4 + ((kk & 7) >> 1);
        int reg = (kk >> 3) & 1;
        int u16idx = (((nt * 8 + kc) * 32 + l) * 2 + reg) * 2 + (kk & 1);
        ((u16*)g_wq_hi)[u16idx] = *(u16*)&h;
        __nv_bfloat16 lo = __float2bfloat16(w - hf);
        ((u16*)g_wq_lo)[u16idx] = *(u16*)&lo;
    }
    if (i < CDIM * CDIM) {
        int o = i / CDIM, c = i % CDIM;
        float w = proj_w[i];
        __nv_bfloat16 h = __float2bfloat16(w);
        float hf = __bfloat162float(h);
        int nt = o >> 3, g = o & 7, kc = c >> 4, kk = c & 15;
        int l = g * 4 + ((kk & 7) >> 1);
        int reg = (kk >> 3) & 1;
        int u16idx = (((nt * 8 + kc) * 32 + l) * 2 + reg) * 2 + (kk & 1);
        ((u16*)g_wp_hi)[u16idx] = *(u16*)&h;
        __nv_bfloat16 lo = __float2bfloat16(w - hf);
        ((u16*)g_wp_lo)[u16idx] = *(u16*)&lo;
    }
    if (i < HEADS * NTOK * NTOK) {
        int h = i / (NTOK * NTOK), r = i % (NTOK * NTOK);
        int m = r / NTOK, n = r % NTOK;
        g_pbias[i] = table[pidx[n * NTOK + m] * HEADS + h];
    }
}

// ================================ main kernel ================================
__global__ void __launch_bounds__(THREADS, 1)
win_attn_kernel(const float* __restrict__ x,
                const float* __restrict__ mask,
                const float* __restrict__ proj_b,
                float* __restrict__ out,
                int nW)
{
    extern __shared__ char smem[];
    const int b = blockIdx.x;
    const int t = threadIdx.x;
    const int wid = t >> 5;
    const int lane = t & 31;

    u32* sAh = (u32*)(smem + OFF_AH);
    u32* sAl = (u32*)(smem + OFF_AL);
    float* s_qkv  = (float*)(smem + OFF_QKV);
    float* s_mask = (float*)(smem + OFF_MASK);
    float* s_p    = (float*)(smem + OFF_P);

    // ---- Phase 0: zero A-fragment region (padding rows 49-63 must stay 0) ----
    {
        uint4* z = (uint4*)(smem + OFF_AH);
        #pragma unroll 1
        for (int i = t; i < 2048; i += THREADS)
            z[i] = make_uint4(0, 0, 0, 0);
    }
    __syncthreads();

    // ---- Phase 1: x -> A-fragments (hi/lo); mask -> smem ----
    {
        const float4* x4 = (const float4*)(x + (size_t)b * NTOK * CDIM);
        #pragma unroll 1
        for (int i = t; i < NTOK * CDIM / 4; i += THREADS) {
            float4 v = __ldg(x4 + i);
            int n = i >> 5, c4 = (i & 31) << 2;
            float h0 = __bfloat162float(__float2bfloat16(v.x));
            float h1 = __bfloat162float(__float2bfloat16(v.y));
            float h2 = __bfloat162float(__float2bfloat16(v.z));
            float h3 = __bfloat162float(__float2bfloat16(v.w));
            int i0 = a_idx(n, c4);
            int i1 = i0 + 4;
            sAh[i0] = bf2(v.x, v.y);
            sAh[i1] = bf2(v.z, v.w);
            sAl[i0] = bf2(v.x - h0, v.y - h1);
            sAl[i1] = bf2(v.z - h2, v.w - h3);
        }
        const float* mrow = mask + (size_t)(b % nW) * NTOK * NTOK;
        #pragma unroll 1
        for (int i = t; i < NTOK * NTOK; i += THREADS)
            s_mask[i] = __ldg(mrow + i);
    }
    __syncthreads();

    // ---- GEMM1: qkv = x @ Wqkv^T; 24 warps = 3 chunks x (2 mtg x 4 ng) ----
    {
        const int wchunk = wid >> 3;          // 0..2
        const int sub    = wid & 7;
        const int mtg    = sub >> 2;          // 0..1 -> m-tiles {2mtg, 2mtg+1}
        const int ng     = sub & 3;           // 0..3 -> n-tiles ng*4..ng*4+3

        float C[2][4][4];
        #pragma unroll
        for (int a = 0; a < 2; a++)
            #pragma unroll
            for (int j = 0; j < 4; j++)
                C[a][j][0] = C[a][j][1] = C[a][j][2] = C[a][j][3] = 0.f;

        #pragma unroll
        for (int kc = 0; kc < 8; kc++) {
            uint4 ah0 = *(const uint4*)(sAh + (((2 * mtg)     * 8 + kc) * 32 + lane) * 4);
            uint4 al0 = *(const uint4*)(sAl + (((2 * mtg)     * 8 + kc) * 32 + lane) * 4);
            uint4 ah1 = *(const uint4*)(sAh + (((2 * mtg + 1) * 8 + kc) * 32 + lane) * 4);
            uint4 al1 = *(const uint4*)(sAl + (((2 * mtg + 1) * 8 + kc) * 32 + lane) * 4);
            #pragma unroll
            for (int j = 0; j < 4; j++) {
                int ntg = wchunk * 16 + ng * 4 + j;
                int bidx = ((ntg * 8 + kc) * 32 + lane) * 2;
                uint2 bh = __ldg((const uint2*)(g_wq_hi + bidx));
                uint2 bl = __ldg((const uint2*)(g_wq_lo + bidx));
                mma16816(C[0][j], ah0, bh);
                mma16816(C[0][j], ah0, bl);
                mma16816(C[0][j], al0, bh);
                mma16816(C[1][j], ah1, bh);
                mma16816(C[1][j], ah1, bl);
                mma16816(C[1][j], al1, bh);
            }
        }
        // store C -> s_qkv fp32
        int g = lane >> 2, t4 = lane & 3;
        #pragma unroll
        for (int a = 0; a < 2; a++) {
            int row0 = (2 * mtg + a) * 16 + g;
            #pragma unroll
            for (int j = 0; j < 4; j++) {
                int col = wchunk * 128 + (ng * 4 + j) * 8 + 2 * t4;
                if (row0 < NTOK)
                    *(float2*)(s_qkv + row0 * QKV_STR + col) = make_float2(C[a][j][0], C[a][j][1]);
                if (row0 + 8 < NTOK)
                    *(float2*)(s_qkv + (row0 + 8) * QKV_STR + col) = make_float2(C[a][j][2], C[a][j][3]);
            }
        }
    }
    __syncthreads();

    // ---- Phase 3: scalar attention per (head, row); logits in p-scratch ----
    if (t < HEADS * NTOK) {
        const int hh = t / NTOK;
        const int nn = t % NTOK;

        ull q2[16];
        const ulonglong2* qrow = (const ulonglong2*)(s_qkv + nn * QKV_STR + hh * HD);
        #pragma unroll
        for (int i = 0; i < 8; i++) {
            ulonglong2 v = qrow[i];
            q2[2 * i] = v.x; q2[2 * i + 1] = v.y;
        }
        float mx = -1e30f;
        const float* pbrow = g_pbias + hh * (NTOK * NTOK) + nn;
        const float* mkrow = s_mask + nn * NTOK;
        float* pcol = s_p + t;                 // private column, stride 196

        #pragma unroll
        for (int m = 0; m < NTOK; m++) {
            const ulonglong2* krow =
                (const ulonglong2*)(s_qkv + m * QKV_STR + CDIM + hh * HD);
            ull sa = 0ull, sb = 0ull;
            #pragma unroll
            for (int i = 0; i < 8; i++) {
                ulonglong2 kv = krow[i];
                sa = fma2(q2[2 * i],     kv.x, sa);
                sb = fma2(q2[2 * i + 1], kv.y, sb);
            }
            float a0, a1, b0, b1; upk2(sa, a0, a1); upk2(sb, b0, b1);
            float dot = (a0 + a1) + (b0 + b1);
            float s = fmaf(dot, SCALE, __ldg(pbrow + m * NTOK) + mkrow[m]);
            pcol[m * 196] = s;
            mx = fmaxf(mx, s);
        }
        ull oacc[16];
        #pragma unroll
        for (int i = 0; i < 16; i++) oacc[i] = 0ull;
        float sum = 0.f;
        #pragma unroll
        for (int m = 0; m < NTOK; m++) {
            float e = __expf(pcol[m * 196] - mx);
            sum += e;
            ull e2 = pk2(e, e);
            const ulonglong2* vrow =
                (const ulonglong2*)(s_qkv + m * QKV_STR + 2 * CDIM + hh * HD);
            #pragma unroll
            for (int i = 0; i < 8; i++) {
                ulonglong2 vv = vrow[i];
                oacc[2 * i]     = fma2(e2, vv.x, oacc[2 * i]);
                oacc[2 * i + 1] = fma2(e2, vv.y, oacc[2 * i + 1]);
            }
        }
        float inv = 1.0f / sum;

        // write o -> A-fragments (hi/lo); rows 49-63 keep zeros (x frags are dead:
        // all GEMM1 reads completed before the preceding __syncthreads)
        #pragma unroll
        for (int i = 0; i < 16; i++) {
            float v0, v1; upk2(oacc[i], v0, v1);
            v0 *= inv; v1 *= inv;
            float h0 = __bfloat162float(__float2bfloat16(v0));
            float h1 = __bfloat162float(__float2bfloat16(v1));
            int c = hh * HD + 2 * i;
            int idx = a_idx(nn, c);
            sAh[idx] = bf2(v0, v1);
            sAl[idx] = bf2(v0 - h0, v1 - h1);
        }
    }
    __syncthreads();

    // ---- GEMM2: out = o @ Wproj^T + bias; 8 warps (2 mtg x 4 ng) ----
    if (wid < 8) {
        const int mtg = (wid >> 2) & 1;
        const int ng  = wid & 3;

        float C[2][4][4];
        #pragma unroll
        for (int a = 0; a < 2; a++)
            #pragma unroll
            for (int j = 0; j < 4; j++)
                C[a][j][0] = C[a][j][1] = C[a][j][2] = C[a][j][3] = 0.f;

        #pragma unroll
        for (int kc = 0; kc < 8; kc++) {
            uint4 ah0 = *(const uint4*)(sAh + (((2 * mtg)     * 8 + kc) * 32 + lane) * 4);
            uint4 al0 = *(const uint4*)(sAl + (((2 * mtg)     * 8 + kc) * 32 + lane) * 4);
            uint4 ah1 = *(const uint4*)(sAh + (((2 * mtg + 1) * 8 + kc) * 32 + lane) * 4);
            uint4 al1 = *(const uint4*)(sAl + (((2 * mtg + 1) * 8 + kc) * 32 + lane) * 4);
            #pragma unroll
            for (int j = 0; j < 4; j++) {
                int ntg = ng * 4 + j;
                int bidx = ((ntg * 8 + kc) * 32 + lane) * 2;
                uint2 bh = __ldg((const uint2*)(g_wp_hi + bidx));
                uint2 bl = __ldg((const uint2*)(g_wp_lo + bidx));
                mma16816(C[0][j], ah0, bh);
                mma16816(C[0][j], ah0, bl);
                mma16816(C[0][j], al0, bh);
                mma16816(C[1][j], ah1, bh);
                mma16816(C[1][j], ah1, bl);
                mma16816(C[1][j], al1, bh);
            }
        }
        int g = lane >> 2, t4 = lane & 3;
        float* ob = out + (size_t)b * NTOK * CDIM;
        #pragma unroll
        for (int a = 0; a < 2; a++) {
            int row0 = (2 * mtg + a) * 16 + g;
            #pragma unroll
            for (int j = 0; j < 4; j++) {
                int col = (ng * 4 + j) * 8 + 2 * t4;
                float2 bias = __ldg((const float2*)(proj_b + col));
                if (row0 < NTOK)
                    *(float2*)(ob + row0 * CDIM + col) =
                        make_float2(C[a][j][0] + bias.x, C[a][j][1] + bias.y);
                if (row0 + 8 < NTOK)
                    *(float2*)(ob + (row0 + 8) * CDIM + col) =
                        make_float2(C[a][j][2] + bias.x, C[a][j][3] + bias.y);
            }
        }
    }
}

extern "C" void kernel_launch(void* const* d_in, const int* in_sizes, int n_in,
                              void* d_out, int out_size)
{
    const float* x      = (const float*)d_in[0];
    const float* qkv_w  = (const float*)d_in[1];
    const float* proj_w = (const float*)d_in[2];
    const float* proj_b = (const float*)d_in[3];
    const float* table  = (const float*)d_in[4];
    const float* mask   = (const float*)d_in[5];
    const int*   pidx   = (const int*)d_in[6];
    float* out = (float*)d_out;

    int B  = in_sizes[0] / (NTOK * CDIM);      // 8192
    int nW = in_sizes[5] / (NTOK * NTOK);      // 1024

    prep_kernel<<<(3 * CDIM * CDIM + 255) / 256, 256>>>(qkv_w, proj_w, table, pidx);

    cudaFuncSetAttribute(win_attn_kernel,
                         cudaFuncAttributeMaxDynamicSharedMemorySize, SMEM_BYTES);
    win_attn_kernel<<<B, THREADS, SMEM_BYTES>>>(x, mask, proj_b, out, nW);
}